// round 1
// baseline (speedup 1.0000x reference)
#include <cuda_runtime.h>
#include <cstdint>

#define MAXN 100096
#define HIDF 64

// ---- scratch (device globals; no allocation allowed) ----
__device__ float g_y[MAXN * HIDF];     // x @ Wl^T  (aggregation source)
__device__ float g_self[MAXN * HIDF];  // x @ Wr^T + bl
__device__ float g_agg[MAXN * HIDF];   // scatter-add accumulator
__device__ float g_h[MAXN * HIDF];     // layer output / next input
__device__ int   g_deg[MAXN];

// ---------------------------------------------------------------------------
// degree: one int atomic per edge
// ---------------------------------------------------------------------------
__global__ void deg_kernel(const int* __restrict__ dst, int* __restrict__ deg, int E) {
    int t = blockIdx.x * blockDim.x + threadIdx.x;
    if (t < E) atomicAdd(&deg[dst[t]], 1);
}

// ---------------------------------------------------------------------------
// fused dual GEMM: Y = X @ Wl^T ; S = X @ Wr^T + bl
// X: [N, KIN] row-major, Wl/Wr: [64, KIN] row-major.
// Block: 256 threads = 16x16; tile 128 nodes x 128 outputs; 8x8 micro-tile
// with stride-16 mapping (conflict-free smem reads).
// ---------------------------------------------------------------------------
template <int KIN>
__global__ void gemm_dual(const float* __restrict__ X,
                          const float* __restrict__ Wl,
                          const float* __restrict__ Wr,
                          const float* __restrict__ bl,
                          float* __restrict__ Y,
                          float* __restrict__ S,
                          int N) {
    constexpr int KB = 16;
    extern __shared__ float sm[];
    float* Wt = sm;                 // [KIN][128]: Wt[k*128+o]
    float* xs = sm + KIN * 128;     // [128][20] (padded rows)

    const int t = threadIdx.x;
    for (int idx = t; idx < KIN * 128; idx += 256) {
        int k = idx >> 7, o = idx & 127;
        Wt[idx] = (o < 64) ? Wl[o * KIN + k] : Wr[(o - 64) * KIN + k];
    }

    const int tx = t & 15, ty = t >> 4;
    float acc[8][8];
#pragma unroll
    for (int i = 0; i < 8; i++)
#pragma unroll
        for (int j = 0; j < 8; j++) acc[i][j] = 0.f;

    const int n0 = blockIdx.x * 128;
    __syncthreads();

    for (int kk = 0; kk < KIN; kk += KB) {
        // stage x tile [128 nodes][KB k] (row stride 20 floats, 16B aligned)
#pragma unroll
        for (int it = 0; it < 2; it++) {
            int idx4 = t + it * 256;            // 0..511 float4 slots
            int r = idx4 >> 2, kq = idx4 & 3;   // node row, k-quad
            int n = n0 + r;
            float4 v = make_float4(0.f, 0.f, 0.f, 0.f);
            if (n < N)
                v = *reinterpret_cast<const float4*>(X + (size_t)n * KIN + kk + kq * 4);
            *reinterpret_cast<float4*>(&xs[r * 20 + kq * 4]) = v;
        }
        __syncthreads();

#pragma unroll
        for (int k = 0; k < KB; k++) {
            float a[8], b[8];
#pragma unroll
            for (int i = 0; i < 8; i++) a[i] = xs[(ty + 16 * i) * 20 + k];
#pragma unroll
            for (int j = 0; j < 8; j++) b[j] = Wt[(kk + k) * 128 + tx + 16 * j];
#pragma unroll
            for (int i = 0; i < 8; i++)
#pragma unroll
                for (int j = 0; j < 8; j++) acc[i][j] += a[i] * b[j];
        }
        __syncthreads();
    }

#pragma unroll
    for (int i = 0; i < 8; i++) {
        int n = n0 + ty + 16 * i;
        if (n >= N) continue;
#pragma unroll
        for (int j = 0; j < 8; j++) {
            int o = tx + 16 * j;
            if (o < 64) Y[(size_t)n * 64 + o] = acc[i][j];
            else        S[(size_t)n * 64 + (o - 64)] = acc[i][j] + bl[o - 64];
        }
    }
}

// ---------------------------------------------------------------------------
// edge aggregation: 16 lanes per edge, each handles one float4 chunk.
// vectorized L2 reduction (red.global.add.v4.f32, sm_90+).
// ---------------------------------------------------------------------------
__global__ void agg_kernel(const int* __restrict__ src, const int* __restrict__ dst,
                           const float* __restrict__ Y, float* __restrict__ agg, int E) {
    int t = blockIdx.x * blockDim.x + threadIdx.x;
    int eid = t >> 4;
    if (eid >= E) return;
    int ch = (t & 15) * 4;
    int s = __ldg(src + eid);
    int d = __ldg(dst + eid);
    float4 v = *reinterpret_cast<const float4*>(Y + (size_t)s * 64 + ch);
    float* p = agg + (size_t)d * 64 + ch;
    asm volatile("red.global.add.v4.f32 [%0], {%1,%2,%3,%4};"
                 :: "l"(p), "f"(v.x), "f"(v.y), "f"(v.z), "f"(v.w)
                 : "memory");
}

// ---------------------------------------------------------------------------
// finalize: h = relu( BN( agg/max(deg,1) + self ) )   — one thread per float4
// ---------------------------------------------------------------------------
__global__ void finalize_kernel(const float* __restrict__ agg,
                                const float* __restrict__ self,
                                const int* __restrict__ deg,
                                const float* __restrict__ gamma,
                                const float* __restrict__ beta,
                                const float* __restrict__ mean,
                                const float* __restrict__ var,
                                float* __restrict__ H, int N) {
    int t = blockIdx.x * blockDim.x + threadIdx.x;
    int n = t >> 4;
    if (n >= N) return;
    int f = (t & 15) * 4;
    float invd = 1.f / fmaxf((float)deg[n], 1.f);
    float4 a = *reinterpret_cast<const float4*>(agg  + (size_t)n * 64 + f);
    float4 s = *reinterpret_cast<const float4*>(self + (size_t)n * 64 + f);
    float4 g = *reinterpret_cast<const float4*>(gamma + f);
    float4 b = *reinterpret_cast<const float4*>(beta  + f);
    float4 m = *reinterpret_cast<const float4*>(mean  + f);
    float4 v = *reinterpret_cast<const float4*>(var   + f);
    float4 o;
    o.x = fmaxf((a.x * invd + s.x - m.x) * rsqrtf(v.x + 1e-5f) * g.x + b.x, 0.f);
    o.y = fmaxf((a.y * invd + s.y - m.y) * rsqrtf(v.y + 1e-5f) * g.y + b.y, 0.f);
    o.z = fmaxf((a.z * invd + s.z - m.z) * rsqrtf(v.z + 1e-5f) * g.z + b.z, 0.f);
    o.w = fmaxf((a.w * invd + s.w - m.w) * rsqrtf(v.w + 1e-5f) * g.w + b.w, 0.f);
    *reinterpret_cast<float4*>(H + (size_t)n * 64 + f) = o;
}

// ---------------------------------------------------------------------------
// head: out[n] = relu(h @ hW1^T + hb1) @ hW2^T + hb2   — one warp per node
// ---------------------------------------------------------------------------
__global__ void head_kernel(const float* __restrict__ H,
                            const float* __restrict__ W1,
                            const float* __restrict__ b1,
                            const float* __restrict__ W2,
                            const float* __restrict__ b2,
                            float* __restrict__ out, int N) {
    __shared__ float w1t[64 * 32];   // w1t[k*32+o] = W1[o*64+k]
    __shared__ float b1s[32];
    __shared__ float w2s[32];
    __shared__ float b2s;
    int t = threadIdx.x;
    for (int idx = t; idx < 64 * 32; idx += blockDim.x) {
        int k = idx >> 5, o = idx & 31;
        w1t[idx] = W1[o * 64 + k];
    }
    if (t < 32) { b1s[t] = b1[t]; w2s[t] = W2[t]; }
    if (t == 0) b2s = b2[0];
    __syncthreads();

    int lane = t & 31;
    int warp = (blockIdx.x * blockDim.x + t) >> 5;
    int nwarp = (gridDim.x * blockDim.x) >> 5;
    for (int n = warp; n < N; n += nwarp) {
        float2 hv = *reinterpret_cast<const float2*>(H + (size_t)n * 64 + lane * 2);
        float acc = 0.f;
#pragma unroll
        for (int q = 0; q < 32; q++) {
            float h0 = __shfl_sync(0xffffffffu, hv.x, q);
            float h1 = __shfl_sync(0xffffffffu, hv.y, q);
            acc += h0 * w1t[(2 * q) * 32 + lane];
            acc += h1 * w1t[(2 * q + 1) * 32 + lane];
        }
        float p = fmaxf(acc + b1s[lane], 0.f) * w2s[lane];
#pragma unroll
        for (int off = 16; off > 0; off >>= 1)
            p += __shfl_down_sync(0xffffffffu, p, off);
        if (lane == 0) out[n] = p + b2s;
    }
}

// ---------------------------------------------------------------------------
extern "C" void kernel_launch(void* const* d_in, const int* in_sizes, int n_in,
                              void* d_out, int out_size) {
    const float* x   = (const float*)d_in[0];
    const int*   ei  = (const int*)d_in[1];
    const float* Wl0 = (const float*)d_in[2];
    const float* Wr0 = (const float*)d_in[3];
    const float* bl0 = (const float*)d_in[4];
    const float* Wl1 = (const float*)d_in[5];
    const float* Wr1 = (const float*)d_in[6];
    const float* bl1 = (const float*)d_in[7];
    const float* Wl2 = (const float*)d_in[8];
    const float* Wr2 = (const float*)d_in[9];
    const float* bl2 = (const float*)d_in[10];
    const float* bng = (const float*)d_in[11];
    const float* bnb = (const float*)d_in[12];
    const float* bnm = (const float*)d_in[13];
    const float* bnv = (const float*)d_in[14];
    const float* hW1 = (const float*)d_in[15];
    const float* hb1 = (const float*)d_in[16];
    const float* hW2 = (const float*)d_in[17];
    const float* hb2 = (const float*)d_in[18];

    const int N = in_sizes[0] / 128;
    const int E = in_sizes[1] / 2;
    const int* src = ei;
    const int* dst = ei + E;

    float *y, *self, *agg, *h;
    int* deg;
    cudaGetSymbolAddress((void**)&y,    g_y);
    cudaGetSymbolAddress((void**)&self, g_self);
    cudaGetSymbolAddress((void**)&agg,  g_agg);
    cudaGetSymbolAddress((void**)&h,    g_h);
    cudaGetSymbolAddress((void**)&deg,  g_deg);

    const int SMEM128 = 128 * 128 * 4 + 128 * 20 * 4;  // 75776
    const int SMEM64  = 64 * 128 * 4 + 128 * 20 * 4;   // 43008
    cudaFuncSetAttribute((const void*)gemm_dual<128>,
                         cudaFuncAttributeMaxDynamicSharedMemorySize, SMEM128);
    cudaFuncSetAttribute((const void*)gemm_dual<64>,
                         cudaFuncAttributeMaxDynamicSharedMemorySize, SMEM64);

    const size_t featBytes = (size_t)N * 64 * sizeof(float);
    const int gblocks = (N + 127) / 128;
    const int eblocks = (E + 255) / 256;
    const int ablocks = (E * 16 + 255) / 256;
    const int fblocks = (N * 16 + 255) / 256;

    // degree (shared by all layers)
    cudaMemsetAsync(deg, 0, (size_t)N * sizeof(int));
    deg_kernel<<<eblocks, 256>>>(dst, deg, E);

    // ---- layer 0 (128 -> 64) ----
    cudaMemsetAsync(agg, 0, featBytes);
    gemm_dual<128><<<gblocks, 256, SMEM128>>>(x, Wl0, Wr0, bl0, y, self, N);
    agg_kernel<<<ablocks, 256>>>(src, dst, y, agg, E);
    finalize_kernel<<<fblocks, 256>>>(agg, self, deg, bng, bnb, bnm, bnv, h, N);

    // ---- layer 1 (64 -> 64) ----
    cudaMemsetAsync(agg, 0, featBytes);
    gemm_dual<64><<<gblocks, 256, SMEM64>>>(h, Wl1, Wr1, bl1, y, self, N);
    agg_kernel<<<ablocks, 256>>>(src, dst, y, agg, E);
    finalize_kernel<<<fblocks, 256>>>(agg, self, deg, bng + 64, bnb + 64, bnm + 64, bnv + 64, h, N);

    // ---- layer 2 (64 -> 64) ----
    cudaMemsetAsync(agg, 0, featBytes);
    gemm_dual<64><<<gblocks, 256, SMEM64>>>(h, Wl2, Wr2, bl2, y, self, N);
    agg_kernel<<<ablocks, 256>>>(src, dst, y, agg, E);
    finalize_kernel<<<fblocks, 256>>>(agg, self, deg, bng + 128, bnb + 128, bnm + 128, bnv + 128, h, N);

    // ---- head ----
    head_kernel<<<(N + 7) / 8, 256>>>(h, hW1, hb1, hW2, hb2, (float*)d_out, N);
}

// round 2
// speedup vs baseline: 1.4477x; 1.4477x over previous
#include <cuda_runtime.h>
#include <cstdint>

#define MAXN 100096
#define MAXE 3200000
#define HIDF 64

// ---- scratch (device globals; no allocation allowed) ----
__device__ float g_y[MAXN * HIDF];      // x @ Wl^T  (aggregation source)
__device__ float g_self[MAXN * HIDF];   // x @ Wr^T + bl
__device__ float g_h[MAXN * HIDF];      // layer output / next input
__device__ int   g_deg[MAXN];
__device__ int   g_rowptr[MAXN + 1];
__device__ int   g_cursor[MAXN];
__device__ int   g_csrc[MAXE];
__device__ int   g_bsum[256];

// ---------------------------------------------------------------------------
// degree: one int atomic per edge
// ---------------------------------------------------------------------------
__global__ void deg_kernel(const int* __restrict__ dst, int* __restrict__ deg, int E) {
    int t = blockIdx.x * blockDim.x + threadIdx.x;
    if (t < E) atomicAdd(&deg[dst[t]], 1);
}

// ---------------------------------------------------------------------------
// CSR build: 3-kernel exclusive scan over degrees, then cursor scatter.
// scan_local: each block scans 1024 degrees (4/thread), writes local-exclusive
//             prefixes into rowptr and its block total into bsum.
// ---------------------------------------------------------------------------
__global__ void scan_local(const int* __restrict__ deg, int* __restrict__ rowptr,
                           int* __restrict__ bsum, int N) {
    __shared__ int sh[256];
    int b = blockIdx.x, t = threadIdx.x;
    int base = b * 1024 + t * 4;
    int v[4];
#pragma unroll
    for (int k = 0; k < 4; k++) v[k] = (base + k < N) ? deg[base + k] : 0;
    int tot = v[0] + v[1] + v[2] + v[3];
    sh[t] = tot;
    __syncthreads();
#pragma unroll
    for (int off = 1; off < 256; off <<= 1) {
        int x = (t >= off) ? sh[t - off] : 0;
        __syncthreads();
        sh[t] += x;
        __syncthreads();
    }
    int excl = sh[t] - tot;   // exclusive prefix of this thread's chunk
    int run = excl;
#pragma unroll
    for (int k = 0; k < 4; k++) {
        if (base + k < N) rowptr[base + k] = run;
        run += v[k];
    }
    if (t == 255) bsum[b] = sh[255];
}

__global__ void scan_blocks(int* __restrict__ bsum, int* __restrict__ rowptr,
                            int nb, int N) {
    if (threadIdx.x == 0 && blockIdx.x == 0) {
        int acc = 0;
        for (int i = 0; i < nb; i++) { int x = bsum[i]; bsum[i] = acc; acc += x; }
        rowptr[N] = acc;
    }
}

__global__ void scan_apply(int* __restrict__ rowptr, int* __restrict__ cursor,
                           const int* __restrict__ bsum, int N) {
    int i = blockIdx.x * blockDim.x + threadIdx.x;
    if (i < N) {
        int r = rowptr[i] + bsum[i >> 10];
        rowptr[i] = r;
        cursor[i] = r;
    }
}

__global__ void scatter_kernel(const int* __restrict__ src, const int* __restrict__ dst,
                               int* __restrict__ cursor, int* __restrict__ csrc, int E) {
    int t = blockIdx.x * blockDim.x + threadIdx.x;
    if (t < E) {
        int d = dst[t];
        int pos = atomicAdd(&cursor[d], 1);
        csrc[pos] = src[t];
    }
}

// ---------------------------------------------------------------------------
// fused dual GEMM: Y = X @ Wl^T ; S = X @ Wr^T + bl
// ---------------------------------------------------------------------------
template <int KIN>
__global__ void gemm_dual(const float* __restrict__ X,
                          const float* __restrict__ Wl,
                          const float* __restrict__ Wr,
                          const float* __restrict__ bl,
                          float* __restrict__ Y,
                          float* __restrict__ S,
                          int N) {
    constexpr int KB = 16;
    extern __shared__ float sm[];
    float* Wt = sm;                 // [KIN][128]: Wt[k*128+o]
    float* xs = sm + KIN * 128;     // [128][20] (padded rows)

    const int t = threadIdx.x;
    for (int idx = t; idx < KIN * 128; idx += 256) {
        int k = idx >> 7, o = idx & 127;
        Wt[idx] = (o < 64) ? Wl[o * KIN + k] : Wr[(o - 64) * KIN + k];
    }

    const int tx = t & 15, ty = t >> 4;
    float acc[8][8];
#pragma unroll
    for (int i = 0; i < 8; i++)
#pragma unroll
        for (int j = 0; j < 8; j++) acc[i][j] = 0.f;

    const int n0 = blockIdx.x * 128;
    __syncthreads();

    for (int kk = 0; kk < KIN; kk += KB) {
#pragma unroll
        for (int it = 0; it < 2; it++) {
            int idx4 = t + it * 256;
            int r = idx4 >> 2, kq = idx4 & 3;
            int n = n0 + r;
            float4 v = make_float4(0.f, 0.f, 0.f, 0.f);
            if (n < N)
                v = *reinterpret_cast<const float4*>(X + (size_t)n * KIN + kk + kq * 4);
            *reinterpret_cast<float4*>(&xs[r * 20 + kq * 4]) = v;
        }
        __syncthreads();

#pragma unroll
        for (int k = 0; k < KB; k++) {
            float a[8], b[8];
#pragma unroll
            for (int i = 0; i < 8; i++) a[i] = xs[(ty + 16 * i) * 20 + k];
#pragma unroll
            for (int j = 0; j < 8; j++) b[j] = Wt[(kk + k) * 128 + tx + 16 * j];
#pragma unroll
            for (int i = 0; i < 8; i++)
#pragma unroll
                for (int j = 0; j < 8; j++) acc[i][j] += a[i] * b[j];
        }
        __syncthreads();
    }

#pragma unroll
    for (int i = 0; i < 8; i++) {
        int n = n0 + ty + 16 * i;
        if (n >= N) continue;
#pragma unroll
        for (int j = 0; j < 8; j++) {
            int o = tx + 16 * j;
            if (o < 64) Y[(size_t)n * 64 + o] = acc[i][j];
            else        S[(size_t)n * 64 + (o - 64)] = acc[i][j] + bl[o - 64];
        }
    }
}

// ---------------------------------------------------------------------------
// pull aggregation + fused finalize:
//   h[n] = relu( BN( mean_{s in nbrs(n)} Y[s] + self[n] ) )
// one warp per node; lane owns a float2 feature slice; neighbor indices
// loaded 32-at-a-time and broadcast via shfl.
// ---------------------------------------------------------------------------
__global__ void agg_pull(const int* __restrict__ rowptr, const int* __restrict__ csrc,
                         const float* __restrict__ Y, const float* __restrict__ self,
                         const float* __restrict__ gamma, const float* __restrict__ beta,
                         const float* __restrict__ mean, const float* __restrict__ var,
                         float* __restrict__ H, int N) {
    const unsigned FULL = 0xffffffffu;
    int warp = (blockIdx.x * blockDim.x + threadIdx.x) >> 5;
    if (warp >= N) return;
    int lane = threadIdx.x & 31;
    int beg = rowptr[warp], end = rowptr[warp + 1];

    float2 a0 = make_float2(0.f, 0.f), a1 = make_float2(0.f, 0.f);
    float2 a2 = make_float2(0.f, 0.f), a3 = make_float2(0.f, 0.f);

    for (int i = beg; i < end; i += 32) {
        int cnt = min(32, end - i);
        int idx = (lane < cnt) ? __ldg(csrc + i + lane) : 0;
        int j = 0;
        for (; j + 4 <= cnt; j += 4) {
            int s0 = __shfl_sync(FULL, idx, j);
            int s1 = __shfl_sync(FULL, idx, j + 1);
            int s2 = __shfl_sync(FULL, idx, j + 2);
            int s3 = __shfl_sync(FULL, idx, j + 3);
            float2 v0 = *reinterpret_cast<const float2*>(Y + (size_t)s0 * 64 + 2 * lane);
            float2 v1 = *reinterpret_cast<const float2*>(Y + (size_t)s1 * 64 + 2 * lane);
            float2 v2 = *reinterpret_cast<const float2*>(Y + (size_t)s2 * 64 + 2 * lane);
            float2 v3 = *reinterpret_cast<const float2*>(Y + (size_t)s3 * 64 + 2 * lane);
            a0.x += v0.x; a0.y += v0.y;
            a1.x += v1.x; a1.y += v1.y;
            a2.x += v2.x; a2.y += v2.y;
            a3.x += v3.x; a3.y += v3.y;
        }
        for (; j < cnt; j++) {
            int s0 = __shfl_sync(FULL, idx, j);
            float2 v0 = *reinterpret_cast<const float2*>(Y + (size_t)s0 * 64 + 2 * lane);
            a0.x += v0.x; a0.y += v0.y;
        }
    }

    float sx = a0.x + a1.x + a2.x + a3.x;
    float sy = a0.y + a1.y + a2.y + a3.y;
    float invd = 1.f / fmaxf((float)(end - beg), 1.f);

    int f = 2 * lane;
    float2 sv = *reinterpret_cast<const float2*>(self + (size_t)warp * 64 + f);
    float2 g  = *reinterpret_cast<const float2*>(gamma + f);
    float2 b  = *reinterpret_cast<const float2*>(beta + f);
    float2 m  = *reinterpret_cast<const float2*>(mean + f);
    float2 vv = *reinterpret_cast<const float2*>(var + f);

    float2 o;
    o.x = fmaxf((sx * invd + sv.x - m.x) * rsqrtf(vv.x + 1e-5f) * g.x + b.x, 0.f);
    o.y = fmaxf((sy * invd + sv.y - m.y) * rsqrtf(vv.y + 1e-5f) * g.y + b.y, 0.f);
    *reinterpret_cast<float2*>(H + (size_t)warp * 64 + f) = o;
}

// ---------------------------------------------------------------------------
// head: out[n] = relu(h @ hW1^T + hb1) @ hW2^T + hb2   — one warp per node
// ---------------------------------------------------------------------------
__global__ void head_kernel(const float* __restrict__ H,
                            const float* __restrict__ W1,
                            const float* __restrict__ b1,
                            const float* __restrict__ W2,
                            const float* __restrict__ b2,
                            float* __restrict__ out, int N) {
    __shared__ float w1t[64 * 32];
    __shared__ float b1s[32];
    __shared__ float w2s[32];
    __shared__ float b2s;
    int t = threadIdx.x;
    for (int idx = t; idx < 64 * 32; idx += blockDim.x) {
        int k = idx >> 5, o = idx & 31;
        w1t[idx] = W1[o * 64 + k];
    }
    if (t < 32) { b1s[t] = b1[t]; w2s[t] = W2[t]; }
    if (t == 0) b2s = b2[0];
    __syncthreads();

    int lane = t & 31;
    int warp = (blockIdx.x * blockDim.x + t) >> 5;
    int nwarp = (gridDim.x * blockDim.x) >> 5;
    for (int n = warp; n < N; n += nwarp) {
        float2 hv = *reinterpret_cast<const float2*>(H + (size_t)n * 64 + lane * 2);
        float acc = 0.f;
#pragma unroll
        for (int q = 0; q < 32; q++) {
            float h0 = __shfl_sync(0xffffffffu, hv.x, q);
            float h1 = __shfl_sync(0xffffffffu, hv.y, q);
            acc += h0 * w1t[(2 * q) * 32 + lane];
            acc += h1 * w1t[(2 * q + 1) * 32 + lane];
        }
        float p = fmaxf(acc + b1s[lane], 0.f) * w2s[lane];
#pragma unroll
        for (int off = 16; off > 0; off >>= 1)
            p += __shfl_down_sync(0xffffffffu, p, off);
        if (lane == 0) out[n] = p + b2s;
    }
}

// ---------------------------------------------------------------------------
extern "C" void kernel_launch(void* const* d_in, const int* in_sizes, int n_in,
                              void* d_out, int out_size) {
    const float* x   = (const float*)d_in[0];
    const int*   ei  = (const int*)d_in[1];
    const float* Wl0 = (const float*)d_in[2];
    const float* Wr0 = (const float*)d_in[3];
    const float* bl0 = (const float*)d_in[4];
    const float* Wl1 = (const float*)d_in[5];
    const float* Wr1 = (const float*)d_in[6];
    const float* bl1 = (const float*)d_in[7];
    const float* Wl2 = (const float*)d_in[8];
    const float* Wr2 = (const float*)d_in[9];
    const float* bl2 = (const float*)d_in[10];
    const float* bng = (const float*)d_in[11];
    const float* bnb = (const float*)d_in[12];
    const float* bnm = (const float*)d_in[13];
    const float* bnv = (const float*)d_in[14];
    const float* hW1 = (const float*)d_in[15];
    const float* hb1 = (const float*)d_in[16];
    const float* hW2 = (const float*)d_in[17];
    const float* hb2 = (const float*)d_in[18];

    const int N = in_sizes[0] / 128;
    const int E = in_sizes[1] / 2;
    const int* src = ei;
    const int* dst = ei + E;

    float *y, *self, *h;
    int *deg, *rowptr, *cursor, *csrc, *bsum;
    cudaGetSymbolAddress((void**)&y,      g_y);
    cudaGetSymbolAddress((void**)&self,   g_self);
    cudaGetSymbolAddress((void**)&h,      g_h);
    cudaGetSymbolAddress((void**)&deg,    g_deg);
    cudaGetSymbolAddress((void**)&rowptr, g_rowptr);
    cudaGetSymbolAddress((void**)&cursor, g_cursor);
    cudaGetSymbolAddress((void**)&csrc,   g_csrc);
    cudaGetSymbolAddress((void**)&bsum,   g_bsum);

    const int SMEM128 = 128 * 128 * 4 + 128 * 20 * 4;  // 75776
    const int SMEM64  = 64 * 128 * 4 + 128 * 20 * 4;   // 43008
    cudaFuncSetAttribute((const void*)gemm_dual<128>,
                         cudaFuncAttributeMaxDynamicSharedMemorySize, SMEM128);
    cudaFuncSetAttribute((const void*)gemm_dual<64>,
                         cudaFuncAttributeMaxDynamicSharedMemorySize, SMEM64);

    const int gblocks = (N + 127) / 128;
    const int eblocks = (E + 255) / 256;
    const int nscan   = (N + 1023) / 1024;
    const int pblocks = (N * 32 + 255) / 256;

    // ---- CSR build (counting sort by dst) ----
    cudaMemsetAsync(deg, 0, (size_t)N * sizeof(int));
    deg_kernel<<<eblocks, 256>>>(dst, deg, E);
    scan_local<<<nscan, 256>>>(deg, rowptr, bsum, N);
    scan_blocks<<<1, 32>>>(bsum, rowptr, nscan, N);
    scan_apply<<<(N + 255) / 256, 256>>>(rowptr, cursor, bsum, N);
    scatter_kernel<<<eblocks, 256>>>(src, dst, cursor, csrc, E);

    // ---- layer 0 (128 -> 64) ----
    gemm_dual<128><<<gblocks, 256, SMEM128>>>(x, Wl0, Wr0, bl0, y, self, N);
    agg_pull<<<pblocks, 256>>>(rowptr, csrc, y, self, bng, bnb, bnm, bnv, h, N);

    // ---- layer 1 (64 -> 64) ----
    gemm_dual<64><<<gblocks, 256, SMEM64>>>(h, Wl1, Wr1, bl1, y, self, N);
    agg_pull<<<pblocks, 256>>>(rowptr, csrc, y, self, bng + 64, bnb + 64, bnm + 64, bnv + 64, h, N);

    // ---- layer 2 (64 -> 64) ----
    gemm_dual<64><<<gblocks, 256, SMEM64>>>(h, Wl2, Wr2, bl2, y, self, N);
    agg_pull<<<pblocks, 256>>>(rowptr, csrc, y, self, bng + 128, bnb + 128, bnm + 128, bnv + 128, h, N);

    // ---- head ----
    head_kernel<<<(N + 7) / 8, 256>>>(h, hW1, hb1, hW2, hb2, (float*)d_out, N);
}

// round 3
// speedup vs baseline: 1.4499x; 1.0015x over previous
#include <cuda_runtime.h>
#include <cstdint>

#define MAXN 100096
#define MAXE 3200000
#define HIDF 64

// ---- scratch (device globals; no allocation allowed) ----
__device__ float g_y[MAXN * HIDF];      // x @ Wl^T  (aggregation source)
__device__ float g_self[MAXN * HIDF];   // x @ Wr^T + bl
__device__ float g_h[MAXN * HIDF];      // layer output / next input
__device__ int   g_deg[MAXN];
__device__ int   g_rowptr[MAXN + 1];
__device__ int   g_cursor[MAXN];
__device__ int   g_csrc[MAXE];
__device__ int   g_bsum[256];

// ---- f32x2 helpers (Blackwell packed fp32) ----
__device__ __forceinline__ unsigned long long pack2(float x, float y) {
    unsigned long long r;
    asm("mov.b64 %0, {%1, %2};" : "=l"(r) : "f"(x), "f"(y));
    return r;
}
__device__ __forceinline__ float2 unpack2(unsigned long long v) {
    float2 r;
    asm("mov.b64 {%0, %1}, %2;" : "=f"(r.x), "=f"(r.y) : "l"(v));
    return r;
}
__device__ __forceinline__ void ffma2(unsigned long long& d,
                                      unsigned long long a, unsigned long long b) {
    asm("fma.rn.f32x2 %0, %1, %2, %3;" : "=l"(d) : "l"(a), "l"(b), "l"(d));
}

// ---------------------------------------------------------------------------
// degree: one int atomic per edge
// ---------------------------------------------------------------------------
__global__ void deg_kernel(const int* __restrict__ dst, int* __restrict__ deg, int E) {
    int t = blockIdx.x * blockDim.x + threadIdx.x;
    if (t < E) atomicAdd(&deg[dst[t]], 1);
}

// ---------------------------------------------------------------------------
// CSR build: scan over degrees, then cursor scatter.
// ---------------------------------------------------------------------------
__global__ void scan_local(const int* __restrict__ deg, int* __restrict__ rowptr,
                           int* __restrict__ bsum, int N) {
    __shared__ int sh[256];
    int b = blockIdx.x, t = threadIdx.x;
    int base = b * 1024 + t * 4;
    int v[4];
#pragma unroll
    for (int k = 0; k < 4; k++) v[k] = (base + k < N) ? deg[base + k] : 0;
    int tot = v[0] + v[1] + v[2] + v[3];
    sh[t] = tot;
    __syncthreads();
#pragma unroll
    for (int off = 1; off < 256; off <<= 1) {
        int x = (t >= off) ? sh[t - off] : 0;
        __syncthreads();
        sh[t] += x;
        __syncthreads();
    }
    int excl = sh[t] - tot;
    int run = excl;
#pragma unroll
    for (int k = 0; k < 4; k++) {
        if (base + k < N) rowptr[base + k] = run;
        run += v[k];
    }
    if (t == 255) bsum[b] = sh[255];
}

// parallel block-sum scan (nb <= 256)
__global__ void scan_blocks(int* __restrict__ bsum, int* __restrict__ rowptr,
                            int nb, int N) {
    __shared__ int sh[256];
    int t = threadIdx.x;
    int v = (t < nb) ? bsum[t] : 0;
    sh[t] = v;
    __syncthreads();
#pragma unroll
    for (int off = 1; off < 256; off <<= 1) {
        int x = (t >= off) ? sh[t - off] : 0;
        __syncthreads();
        sh[t] += x;
        __syncthreads();
    }
    if (t < nb) bsum[t] = sh[t] - v;
    if (t == nb - 1) rowptr[N] = sh[t];
}

__global__ void scan_apply(int* __restrict__ rowptr, int* __restrict__ cursor,
                           const int* __restrict__ bsum, int N) {
    int i = blockIdx.x * blockDim.x + threadIdx.x;
    if (i < N) {
        int r = rowptr[i] + bsum[i >> 10];
        rowptr[i] = r;
        cursor[i] = r;
    }
}

__global__ void scatter_kernel(const int* __restrict__ src, const int* __restrict__ dst,
                               int* __restrict__ cursor, int* __restrict__ csrc, int E) {
    int t = blockIdx.x * blockDim.x + threadIdx.x;
    if (t < E) {
        int d = dst[t];
        int pos = atomicAdd(&cursor[d], 1);
        csrc[pos] = src[t];
    }
}

// ---------------------------------------------------------------------------
// fused dual GEMM with packed f32x2 FMA:
//   Y = X @ Wl^T ; S = X @ Wr^T + bl
// 256 threads = 16x16; tile 128 nodes x 128 outputs.
// Each thread: 8 rows (ty+16i) x 4 contiguous output PAIRS (o = 2*tx + 32*jp).
// ---------------------------------------------------------------------------
template <int KIN>
__global__ void gemm_dual(const float* __restrict__ X,
                          const float* __restrict__ Wl,
                          const float* __restrict__ Wr,
                          const float* __restrict__ bl,
                          float* __restrict__ Y,
                          float* __restrict__ S,
                          int N) {
    constexpr int KB = 16;
    extern __shared__ float sm[];
    float* Wt = sm;                 // [KIN][128]: Wt[k*128+o]
    float* xs = sm + KIN * 128;     // [128][20] (padded rows)

    const int t = threadIdx.x;
    for (int idx = t; idx < KIN * 128; idx += 256) {
        int k = idx >> 7, o = idx & 127;
        Wt[idx] = (o < 64) ? Wl[o * KIN + k] : Wr[(o - 64) * KIN + k];
    }

    const int tx = t & 15, ty = t >> 4;
    unsigned long long acc[8][4];
#pragma unroll
    for (int i = 0; i < 8; i++)
#pragma unroll
        for (int jp = 0; jp < 4; jp++) acc[i][jp] = 0ull;

    const int n0 = blockIdx.x * 128;
    __syncthreads();

    for (int kk = 0; kk < KIN; kk += KB) {
#pragma unroll
        for (int it = 0; it < 2; it++) {
            int idx4 = t + it * 256;
            int r = idx4 >> 2, kq = idx4 & 3;
            int n = n0 + r;
            float4 v = make_float4(0.f, 0.f, 0.f, 0.f);
            if (n < N)
                v = *reinterpret_cast<const float4*>(X + (size_t)n * KIN + kk + kq * 4);
            *reinterpret_cast<float4*>(&xs[r * 20 + kq * 4]) = v;
        }
        __syncthreads();

#pragma unroll
        for (int k = 0; k < KB; k++) {
            unsigned long long a2[8], b2[4];
#pragma unroll
            for (int i = 0; i < 8; i++) {
                float a = xs[(ty + 16 * i) * 20 + k];
                a2[i] = pack2(a, a);
            }
#pragma unroll
            for (int jp = 0; jp < 4; jp++)
                b2[jp] = *reinterpret_cast<const unsigned long long*>(
                             &Wt[(kk + k) * 128 + 2 * tx + 32 * jp]);
#pragma unroll
            for (int i = 0; i < 8; i++)
#pragma unroll
                for (int jp = 0; jp < 4; jp++)
                    ffma2(acc[i][jp], a2[i], b2[jp]);
        }
        __syncthreads();
    }

    // bias pairs for the S half (jp = 2,3)
    float2 blv[2];
#pragma unroll
    for (int jp = 0; jp < 2; jp++)
        blv[jp] = *reinterpret_cast<const float2*>(bl + 2 * tx + 32 * jp);

#pragma unroll
    for (int i = 0; i < 8; i++) {
        int n = n0 + ty + 16 * i;
        if (n >= N) continue;
#pragma unroll
        for (int jp = 0; jp < 4; jp++) {
            float2 r = unpack2(acc[i][jp]);
            int o = 2 * tx + 32 * jp;
            if (jp < 2) {
                *reinterpret_cast<float2*>(Y + (size_t)n * 64 + o) = r;
            } else {
                r.x += blv[jp - 2].x;
                r.y += blv[jp - 2].y;
                *reinterpret_cast<float2*>(S + (size_t)n * 64 + (o - 64)) = r;
            }
        }
    }
}

// ---------------------------------------------------------------------------
// pull aggregation + fused finalize:
//   h[n] = relu( BN( mean_{s in nbrs(n)} Y[s] + self[n] ) )
// 16 lanes per node (2 nodes/warp); each lane owns a float4 feature slice.
// ---------------------------------------------------------------------------
__global__ void agg_pull(const int* __restrict__ rowptr, const int* __restrict__ csrc,
                         const float* __restrict__ Y, const float* __restrict__ self,
                         const float* __restrict__ gamma, const float* __restrict__ beta,
                         const float* __restrict__ mean, const float* __restrict__ var,
                         float* __restrict__ H, int N) {
    int node = (blockIdx.x * blockDim.x + threadIdx.x) >> 4;
    if (node >= N) return;
    int sl = threadIdx.x & 15;                    // sublane within 16-group
    unsigned mask = (threadIdx.x & 16) ? 0xffff0000u : 0x0000ffffu;
    int beg = rowptr[node], end = rowptr[node + 1];

    float4 a0 = make_float4(0.f, 0.f, 0.f, 0.f);
    float4 a1 = make_float4(0.f, 0.f, 0.f, 0.f);
    float4 a2 = make_float4(0.f, 0.f, 0.f, 0.f);
    float4 a3 = make_float4(0.f, 0.f, 0.f, 0.f);

    const float4* Y4 = reinterpret_cast<const float4*>(Y);
    for (int i = beg; i < end; i += 16) {
        int cnt = min(16, end - i);
        int idx = (sl < cnt) ? __ldg(csrc + i + sl) : 0;
        int j = 0;
        for (; j + 4 <= cnt; j += 4) {
            int s0 = __shfl_sync(mask, idx, j,     16);
            int s1 = __shfl_sync(mask, idx, j + 1, 16);
            int s2 = __shfl_sync(mask, idx, j + 2, 16);
            int s3 = __shfl_sync(mask, idx, j + 3, 16);
            float4 v0 = __ldg(Y4 + (size_t)s0 * 16 + sl);
            float4 v1 = __ldg(Y4 + (size_t)s1 * 16 + sl);
            float4 v2 = __ldg(Y4 + (size_t)s2 * 16 + sl);
            float4 v3 = __ldg(Y4 + (size_t)s3 * 16 + sl);
            a0.x += v0.x; a0.y += v0.y; a0.z += v0.z; a0.w += v0.w;
            a1.x += v1.x; a1.y += v1.y; a1.z += v1.z; a1.w += v1.w;
            a2.x += v2.x; a2.y += v2.y; a2.z += v2.z; a2.w += v2.w;
            a3.x += v3.x; a3.y += v3.y; a3.z += v3.z; a3.w += v3.w;
        }
        for (; j < cnt; j++) {
            int s0 = __shfl_sync(mask, idx, j, 16);
            float4 v0 = __ldg(Y4 + (size_t)s0 * 16 + sl);
            a0.x += v0.x; a0.y += v0.y; a0.z += v0.z; a0.w += v0.w;
        }
    }

    float4 s4;
    s4.x = a0.x + a1.x + a2.x + a3.x;
    s4.y = a0.y + a1.y + a2.y + a3.y;
    s4.z = a0.z + a1.z + a2.z + a3.z;
    s4.w = a0.w + a1.w + a2.w + a3.w;
    float invd = 1.f / fmaxf((float)(end - beg), 1.f);

    int f = 4 * sl;
    float4 sv = *reinterpret_cast<const float4*>(self + (size_t)node * 64 + f);
    float4 g  = *reinterpret_cast<const float4*>(gamma + f);
    float4 b  = *reinterpret_cast<const float4*>(beta + f);
    float4 m  = *reinterpret_cast<const float4*>(mean + f);
    float4 vv = *reinterpret_cast<const float4*>(var + f);

    float4 o;
    o.x = fmaxf((s4.x * invd + sv.x - m.x) * rsqrtf(vv.x + 1e-5f) * g.x + b.x, 0.f);
    o.y = fmaxf((s4.y * invd + sv.y - m.y) * rsqrtf(vv.y + 1e-5f) * g.y + b.y, 0.f);
    o.z = fmaxf((s4.z * invd + sv.z - m.z) * rsqrtf(vv.z + 1e-5f) * g.z + b.z, 0.f);
    o.w = fmaxf((s4.w * invd + sv.w - m.w) * rsqrtf(vv.w + 1e-5f) * g.w + b.w, 0.f);
    *reinterpret_cast<float4*>(H + (size_t)node * 64 + f) = o;
}

// ---------------------------------------------------------------------------
// head: out[n] = relu(h @ hW1^T + hb1) @ hW2^T + hb2   — one warp per node
// ---------------------------------------------------------------------------
__global__ void head_kernel(const float* __restrict__ H,
                            const float* __restrict__ W1,
                            const float* __restrict__ b1,
                            const float* __restrict__ W2,
                            const float* __restrict__ b2,
                            float* __restrict__ out, int N) {
    __shared__ float w1t[64 * 32];
    __shared__ float b1s[32];
    __shared__ float w2s[32];
    __shared__ float b2s;
    int t = threadIdx.x;
    for (int idx = t; idx < 64 * 32; idx += blockDim.x) {
        int k = idx >> 5, o = idx & 31;
        w1t[idx] = W1[o * 64 + k];
    }
    if (t < 32) { b1s[t] = b1[t]; w2s[t] = W2[t]; }
    if (t == 0) b2s = b2[0];
    __syncthreads();

    int lane = t & 31;
    int warp = (blockIdx.x * blockDim.x + t) >> 5;
    int nwarp = (gridDim.x * blockDim.x) >> 5;
    for (int n = warp; n < N; n += nwarp) {
        float2 hv = *reinterpret_cast<const float2*>(H + (size_t)n * 64 + lane * 2);
        float acc = 0.f;
#pragma unroll
        for (int q = 0; q < 32; q++) {
            float h0 = __shfl_sync(0xffffffffu, hv.x, q);
            float h1 = __shfl_sync(0xffffffffu, hv.y, q);
            acc += h0 * w1t[(2 * q) * 32 + lane];
            acc += h1 * w1t[(2 * q + 1) * 32 + lane];
        }
        float p = fmaxf(acc + b1s[lane], 0.f) * w2s[lane];
#pragma unroll
        for (int off = 16; off > 0; off >>= 1)
            p += __shfl_down_sync(0xffffffffu, p, off);
        if (lane == 0) out[n] = p + b2s;
    }
}

// ---------------------------------------------------------------------------
extern "C" void kernel_launch(void* const* d_in, const int* in_sizes, int n_in,
                              void* d_out, int out_size) {
    const float* x   = (const float*)d_in[0];
    const int*   ei  = (const int*)d_in[1];
    const float* Wl0 = (const float*)d_in[2];
    const float* Wr0 = (const float*)d_in[3];
    const float* bl0 = (const float*)d_in[4];
    const float* Wl1 = (const float*)d_in[5];
    const float* Wr1 = (const float*)d_in[6];
    const float* bl1 = (const float*)d_in[7];
    const float* Wl2 = (const float*)d_in[8];
    const float* Wr2 = (const float*)d_in[9];
    const float* bl2 = (const float*)d_in[10];
    const float* bng = (const float*)d_in[11];
    const float* bnb = (const float*)d_in[12];
    const float* bnm = (const float*)d_in[13];
    const float* bnv = (const float*)d_in[14];
    const float* hW1 = (const float*)d_in[15];
    const float* hb1 = (const float*)d_in[16];
    const float* hW2 = (const float*)d_in[17];
    const float* hb2 = (const float*)d_in[18];

    const int N = in_sizes[0] / 128;
    const int E = in_sizes[1] / 2;
    const int* src = ei;
    const int* dst = ei + E;

    float *y, *self, *h;
    int *deg, *rowptr, *cursor, *csrc, *bsum;
    cudaGetSymbolAddress((void**)&y,      g_y);
    cudaGetSymbolAddress((void**)&self,   g_self);
    cudaGetSymbolAddress((void**)&h,      g_h);
    cudaGetSymbolAddress((void**)&deg,    g_deg);
    cudaGetSymbolAddress((void**)&rowptr, g_rowptr);
    cudaGetSymbolAddress((void**)&cursor, g_cursor);
    cudaGetSymbolAddress((void**)&csrc,   g_csrc);
    cudaGetSymbolAddress((void**)&bsum,   g_bsum);

    const int SMEM128 = 128 * 128 * 4 + 128 * 20 * 4;  // 75776
    const int SMEM64  = 64 * 128 * 4 + 128 * 20 * 4;   // 43008
    cudaFuncSetAttribute((const void*)gemm_dual<128>,
                         cudaFuncAttributeMaxDynamicSharedMemorySize, SMEM128);
    cudaFuncSetAttribute((const void*)gemm_dual<64>,
                         cudaFuncAttributeMaxDynamicSharedMemorySize, SMEM64);

    const int gblocks = (N + 127) / 128;
    const int eblocks = (E + 255) / 256;
    const int nscan   = (N + 1023) / 1024;
    const int pblocks = (N * 16 + 255) / 256;

    // ---- CSR build (counting sort by dst) ----
    cudaMemsetAsync(deg, 0, (size_t)N * sizeof(int));
    deg_kernel<<<eblocks, 256>>>(dst, deg, E);
    scan_local<<<nscan, 256>>>(deg, rowptr, bsum, N);
    scan_blocks<<<1, 256>>>(bsum, rowptr, nscan, N);
    scan_apply<<<(N + 255) / 256, 256>>>(rowptr, cursor, bsum, N);
    scatter_kernel<<<eblocks, 256>>>(src, dst, cursor, csrc, E);

    // ---- layer 0 (128 -> 64) ----
    gemm_dual<128><<<gblocks, 256, SMEM128>>>(x, Wl0, Wr0, bl0, y, self, N);
    agg_pull<<<pblocks, 256>>>(rowptr, csrc, y, self, bng, bnb, bnm, bnv, h, N);

    // ---- layer 1 (64 -> 64) ----
    gemm_dual<64><<<gblocks, 256, SMEM64>>>(h, Wl1, Wr1, bl1, y, self, N);
    agg_pull<<<pblocks, 256>>>(rowptr, csrc, y, self, bng + 64, bnb + 64, bnm + 64, bnv + 64, h, N);

    // ---- layer 2 (64 -> 64) ----
    gemm_dual<64><<<gblocks, 256, SMEM64>>>(h, Wl2, Wr2, bl2, y, self, N);
    agg_pull<<<pblocks, 256>>>(rowptr, csrc, y, self, bng + 128, bnb + 128, bnm + 128, bnv + 128, h, N);

    // ---- head ----
    head_kernel<<<(N + 7) / 8, 256>>>(h, hW1, hb1, hW2, hb2, (float*)d_out, N);
}